// round 11
// baseline (speedup 1.0000x reference)
#include <cuda_runtime.h>
#include <cstdint>

// Problem dims
#define B_   512
#define T_   1024
#define D_   64
#define H_   256
#define O_   64
#define KTOT 320           // combined [x(64) | h(256)]

#define ROWS 4
#define NCTA (B_/ROWS)     // 128
#define NTHR 512
#define KBN  4             // k-slices
#define KSL  80            // k per slice
#define VS4  84            // padded slice stride (floats): kb offsets {0,80,32,112} mod 128 B
#define RSTR (KBN*VS4)     // 336 floats per row
#define VBUF (ROWS*RSTR)   // 1344 floats (single buffer)

typedef unsigned long long ull;

// Per-thread W: 2 j x 80 k = 160 floats = 80 ull = 2 jj x 40 k-pairs (kp)
//   kp  0..11 -> registers  (g_Wr,  24 ull/thread)
//   kp 12..31 -> SMEM       (g_Ws,  20 ulonglong2/thread = 160 KB staged)
//   kp 32..39 -> L2 stream  (g_Wl,   8 ulonglong2/thread, 2 prefetch waves)
__device__ ull        g_Wr[24*NTHR];
__device__ ulonglong2 g_Ws[20*NTHR];
__device__ ulonglong2 g_Wl[8*NTHR];

__device__ __forceinline__ ull fma2(ull a, ull b, ull c) {
    ull d; asm("fma.rn.f32x2 %0, %1, %2, %3;" : "=l"(d) : "l"(a), "l"(b), "l"(c));
    return d;
}
__device__ __forceinline__ ull add2(ull a, ull b) {
    ull d; asm("add.rn.f32x2 %0, %1, %2;" : "=l"(d) : "l"(a), "l"(b));
    return d;
}

// Pack Wf[H, D+H] into the three per-thread layouts.
__global__ void ltc_prep(const float* __restrict__ Wf) {
    int idx = blockIdx.x * blockDim.x + threadIdx.x;
    if (idx >= 80*NTHR) return;
    int tid = idx & (NTHR-1);
    int p   = idx >> 9;            // 0..79
    int jj  = p / 40, kp = p % 40;
    int warp = tid >> 5, lane = tid & 31;
    int kb = lane & 3;
    int g  = warp * 8 + (lane >> 2);   // 0..127
    int j  = 2*g + jj;
    int k  = kb*KSL + 2*kp;
    float lo = Wf[j*KTOT + k];
    float hi = Wf[j*KTOT + k + 1];
    ull val = ((ull)__float_as_uint(hi) << 32) | __float_as_uint(lo);
    if (kp < 12) {
        g_Wr[(jj*12 + kp)*NTHR + tid] = val;
    } else if (kp < 32) {
        int u = kp - 12;                 // 0..19
        int e = (u >> 1)*2 + jj;         // entry 0..19 for (chunk 6+u/2, jj)
        ((ull*)g_Ws)[(e*NTHR + tid)*2 + (u & 1)] = val;
    } else {
        int m = kp - 32;                 // 0..7
        int s = (m >> 1)*2 + jj;         // chunks 16..19 -> slots 0..7
        ((ull*)g_Wl)[(s*NTHR + tid)*2 + (m & 1)] = val;
    }
}

// SMEM (floats): s_w 20*512 ulonglong2 = 40960 f | s_v 1344 f | s_zp 16*256 ull = 8192 f
#define SM_V   (20*NTHR*4)
#define SM_ZP  (SM_V + VBUF)
#define SM_TOT (SM_ZP + 8192)          // 50,496 floats = 201,984 B

__global__ __launch_bounds__(NTHR, 1)
void ltc_main(const float* __restrict__ x,
              const float* __restrict__ bf,
              const float* __restrict__ tau,
              const float* __restrict__ A,
              const float* __restrict__ Wo,
              const float* __restrict__ bo,
              float* __restrict__ out)
{
    extern __shared__ float sm[];
    ulonglong2* s_w  = (ulonglong2*)sm;
    float*      s_v  = sm + SM_V;
    ull*        s_zp = (ull*)(sm + SM_ZP);

    const int tid  = threadIdx.x;
    const int lane = tid & 31;
    const int kb   = lane & 3;
    const int g    = (tid >> 5)*8 + (lane >> 2);  // 0..127
    const int row0 = blockIdx.x * ROWS;

    // ---- stage SMEM-W (coalesced) ----
    for (int e = 0; e < 20; e++) s_w[e*NTHR + tid] = g_Ws[e*NTHR + tid];

    // ---- W registers (24 ull = 48 regs) ----
    ull w2[24];
#pragma unroll
    for (int p = 0; p < 24; p++) w2[p] = g_Wr[p*NTHR + tid];

    // ---- updater state: thread handles (uj, rows rr and rr+2) ----
    const int uj = tid & 255;
    const int rr = tid >> 8;
    const float bfj = bf[uj];
    const float itj = expf(-tau[uj]);
    const float Aj  = A[uj];
    float h_a = 0.f, h_b = 0.f;
    const int hk   = 64 + uj;
    const int hadr = (hk/KSL)*VS4 + (hk % KSL);

    // ---- x writer (threads < 256) ----
    const int xr = (tid >> 6) & 3, xd = tid & 63;
    const float* xptr = x + (size_t)(row0 + xr) * T_ * D_ + xd;

    // ---- init v: zeros, then x(t=0) ----
    for (int i = tid; i < VBUF; i += NTHR) s_v[i] = 0.f;
    __syncthreads();
    if (tid < 256) s_v[xr*RSTR + xd] = xptr[0];
    __syncthreads();

    const float* vbk = s_v + kb*VS4;
    const int j2 = 2*g;

    // ================= recurrent loop =================
    for (int t = 0; t < T_; ++t) {
        // L2 wave A: chunks 16,17 (consumed ~600+ cyc later)
        ulonglong2 rA0 = g_Wl[0*NTHR + tid];
        ulonglong2 rA1 = g_Wl[1*NTHR + tid];
        ulonglong2 rA2 = g_Wl[2*NTHR + tid];
        ulonglong2 rA3 = g_Wl[3*NTHR + tid];

        float x_pre = 0.f;
        if (tid < 256 && t + 1 < T_) x_pre = xptr[(t + 1) * D_];

        ull acc[8];
#pragma unroll
        for (int i = 0; i < 8; i++) acc[i] = 0ull;

#define ROWS_FMA(WA0,WB0,WA1,WB1)                                          \
        {                                                                  \
            ulonglong2 v0 = *(const ulonglong2*)(vbk + 0*RSTR + 4*q);      \
            ulonglong2 v1 = *(const ulonglong2*)(vbk + 1*RSTR + 4*q);      \
            ulonglong2 v2 = *(const ulonglong2*)(vbk + 2*RSTR + 4*q);      \
            ulonglong2 v3 = *(const ulonglong2*)(vbk + 3*RSTR + 4*q);      \
            acc[0] = fma2(WA0, v0.x, acc[0]); acc[0] = fma2(WB0, v0.y, acc[0]); \
            acc[1] = fma2(WA0, v1.x, acc[1]); acc[1] = fma2(WB0, v1.y, acc[1]); \
            acc[2] = fma2(WA0, v2.x, acc[2]); acc[2] = fma2(WB0, v2.y, acc[2]); \
            acc[3] = fma2(WA0, v3.x, acc[3]); acc[3] = fma2(WB0, v3.y, acc[3]); \
            acc[4] = fma2(WA1, v0.x, acc[4]); acc[4] = fma2(WB1, v0.y, acc[4]); \
            acc[5] = fma2(WA1, v1.x, acc[5]); acc[5] = fma2(WB1, v1.y, acc[5]); \
            acc[6] = fma2(WA1, v2.x, acc[6]); acc[6] = fma2(WB1, v2.y, acc[6]); \
            acc[7] = fma2(WA1, v3.x, acc[7]); acc[7] = fma2(WB1, v3.y, acc[7]); \
        }

        // ---- chunks 0..5: W from registers ----
#pragma unroll
        for (int q = 0; q < 6; q++) {
            ROWS_FMA(w2[2*q], w2[2*q+1], w2[12+2*q], w2[12+2*q+1]);
        }

        // ---- chunks 6..10: W from SMEM ----
#pragma unroll
        for (int q = 6; q < 11; q++) {
            ulonglong2 wj0 = s_w[((q-6)*2 + 0)*NTHR + tid];
            ulonglong2 wj1 = s_w[((q-6)*2 + 1)*NTHR + tid];
            ROWS_FMA(wj0.x, wj0.y, wj1.x, wj1.y);
        }

        // L2 wave B: chunks 18,19
        ulonglong2 rB0 = g_Wl[4*NTHR + tid];
        ulonglong2 rB1 = g_Wl[5*NTHR + tid];
        ulonglong2 rB2 = g_Wl[6*NTHR + tid];
        ulonglong2 rB3 = g_Wl[7*NTHR + tid];

        // ---- chunks 11..15: W from SMEM ----
#pragma unroll
        for (int q = 11; q < 16; q++) {
            ulonglong2 wj0 = s_w[((q-6)*2 + 0)*NTHR + tid];
            ulonglong2 wj1 = s_w[((q-6)*2 + 1)*NTHR + tid];
            ROWS_FMA(wj0.x, wj0.y, wj1.x, wj1.y);
        }

        // ---- chunks 16..19: W from L2 waves ----
        { const int q = 16; ROWS_FMA(rA0.x, rA0.y, rA1.x, rA1.y); }
        { const int q = 17; ROWS_FMA(rA2.x, rA2.y, rA3.x, rA3.y); }
        { const int q = 18; ROWS_FMA(rB0.x, rB0.y, rB1.x, rB1.y); }
        { const int q = 19; ROWS_FMA(rB2.x, rB2.y, rB3.x, rB3.y); }
#undef ROWS_FMA

        // ---- post packed partials (no shfl): zp[(kb*4+r)*256 + j] ----
#pragma unroll
        for (int jj = 0; jj < 2; jj++)
#pragma unroll
            for (int r = 0; r < 4; r++)
                s_zp[(kb*4 + r)*256 + j2 + jj] = acc[jj*4 + r];
        __syncthreads();

        // ---- reduce 4 kb-partials + gate + state update ----
        {
            ull za = add2(add2(s_zp[(rr     )*256 + uj], s_zp[(4 + rr )*256 + uj]),
                          add2(s_zp[(8 + rr )*256 + uj], s_zp[(12 + rr)*256 + uj]));
            ull zb = add2(add2(s_zp[(rr + 2 )*256 + uj], s_zp[(6 + rr )*256 + uj]),
                          add2(s_zp[(10 + rr)*256 + uj], s_zp[(14 + rr)*256 + uj]));
            float zA = __uint_as_float((unsigned)za)
                     + __uint_as_float((unsigned)(za >> 32)) + bfj;
            float zB = __uint_as_float((unsigned)zb)
                     + __uint_as_float((unsigned)(zb >> 32)) + bfj;
            float fA = __fdividef(1.f, 1.f + __expf(-zA));
            float fB = __fdividef(1.f, 1.f + __expf(-zB));
            h_a += (-(itj + fA) * h_a + fA * Aj) * 0.1f;
            h_b += (-(itj + fB) * h_b + fB * Aj) * 0.1f;
            s_v[rr*RSTR + hadr]     = h_a;
            s_v[(rr+2)*RSTR + hadr] = h_b;
            if (tid < 256) s_v[xr*RSTR + xd] = x_pre;
        }
        __syncthreads();
    }

    // ================= output projection =================
    float* s_hl = (float*)s_zp;           // [r][j]
    s_hl[rr*256 + uj]     = h_a;
    s_hl[(rr+2)*256 + uj] = h_b;
    float* s_wo = (float*)s_w;            // reuse W region: [o][260]
    __syncthreads();
    for (int i = tid; i < 64*256; i += NTHR) {
        int o = i >> 8, q = i & 255;
        s_wo[o*260 + q] = Wo[i];
    }
    __syncthreads();

    if (tid < 256) {
        int r = tid >> 6, o = tid & 63;
        const float4* w4 = (const float4*)(s_wo + o*260);
        const float4* h4 = (const float4*)(s_hl + r*256);
        float s = bo[o];
#pragma unroll
        for (int q = 0; q < 64; q++) {
            float4 w = w4[q];
            float4 h = h4[q];
            s += w.x*h.x + w.y*h.y + w.z*h.z + w.w*h.w;
        }
        out[(row0 + r)*O_ + o] = s;
    }
}

extern "C" void kernel_launch(void* const* d_in, const int* in_sizes, int n_in,
                              void* d_out, int out_size)
{
    (void)in_sizes; (void)n_in; (void)out_size;
    const float* x   = (const float*)d_in[0];
    const float* Wf  = (const float*)d_in[1];
    const float* bf  = (const float*)d_in[2];
    const float* tau = (const float*)d_in[3];
    const float* A   = (const float*)d_in[4];
    const float* Wo  = (const float*)d_in[5];
    const float* bo  = (const float*)d_in[6];
    float* out = (float*)d_out;

    const int smem_bytes = SM_TOT * (int)sizeof(float);  // 201,984 B
    cudaFuncSetAttribute(ltc_main,
                         cudaFuncAttributeMaxDynamicSharedMemorySize, smem_bytes);

    ltc_prep<<<(80*NTHR + NTHR - 1) / NTHR, NTHR>>>(Wf);
    ltc_main<<<NCTA, NTHR, smem_bytes>>>(x, bf, tau, A, Wo, bo, out);
}

// round 12
// speedup vs baseline: 2.3926x; 2.3926x over previous
#include <cuda_runtime.h>
#include <cstdint>

// Problem dims
#define B_   512
#define T_   1024
#define D_   64
#define H_   256
#define O_   64
#define KTOT 320           // combined [x(64) | h(256)]

#define ROWS 4
#define NCTA (B_/ROWS)     // 128
#define NTHR 256
#define KSL  80            // k per kb-slice
#define VS4  84            // padded slice stride: kb bank-quads {0-3,20-23,8-11,28-31}
#define RSTR (4*VS4)       // 336 floats per row
#define VBUF (ROWS*RSTR)   // 1344 floats (single buffer)

// W chunk classes (20 chunks of 4 k per slice)
#define NCH_RF 7           // chunks 0..6   -> registers (56 ull = 112 regs)
#define NCH_SM 11          // chunks 7..17  -> SMEM (44 ulonglong2 = 176 KB staged)
#define NCH_L2 2           // chunks 18,19  -> L2 stream (8 ulonglong2, 2 waves)

#define ZSTR 513           // zp kb-stride in ulonglong2 (padded)

typedef unsigned long long ull;

__device__ ull        g_Wr[NCH_RF*4*2*NTHR];   // 56*256 ull
__device__ ulonglong2 g_Ws[NCH_SM*4*NTHR];     // 44*256
__device__ ulonglong2 g_Wl[NCH_L2*4*NTHR];     // 8*256

__device__ __forceinline__ ull fma2(ull a, ull b, ull c) {
    ull d; asm("fma.rn.f32x2 %0, %1, %2, %3;" : "=l"(d) : "l"(a), "l"(b), "l"(c));
    return d;
}
__device__ __forceinline__ ull add2(ull a, ull b) {
    ull d; asm("add.rn.f32x2 %0, %1, %2;" : "=l"(d) : "l"(a), "l"(b));
    return d;
}

// Pack Wf[H, D+H] into per-thread layouts. One prep thread per ulonglong2 (4 floats).
__global__ void ltc_prep(const float* __restrict__ Wf) {
    int idx = blockIdx.x * blockDim.x + threadIdx.x;
    if (idx >= 80*NTHR) return;
    int tid  = idx & (NTHR-1);
    int u2   = idx >> 8;             // 0..79
    int chunk = u2 >> 2, jj = u2 & 3;
    int lane = tid & 31;
    int kb   = lane & 3;
    int g    = (tid >> 5)*8 + (lane >> 2);   // 0..63
    int j    = g*4 + jj;
    int k0   = kb*KSL + chunk*4;             // combined k (cols of Wf are [x|h])
    const float* src = Wf + j*KTOT + k0;
    ull lo = ((ull)__float_as_uint(src[1]) << 32) | __float_as_uint(src[0]);
    ull hi = ((ull)__float_as_uint(src[3]) << 32) | __float_as_uint(src[2]);
    if (chunk < NCH_RF) {
        int p = (chunk*4 + jj)*2;
        g_Wr[(p+0)*NTHR + tid] = lo;
        g_Wr[(p+1)*NTHR + tid] = hi;
    } else if (chunk < NCH_RF + NCH_SM) {
        int e = (chunk - NCH_RF)*4 + jj;
        g_Ws[e*NTHR + tid] = make_ulonglong2(lo, hi);
    } else {
        int s = (chunk - (NCH_RF + NCH_SM))*4 + jj;
        g_Wl[s*NTHR + tid] = make_ulonglong2(lo, hi);
    }
}

// SMEM: s_w 44*256 ul2 (180224 B) | s_v 1344 f (5376 B) | zp 4*513 ul2 (32832 B)
#define SM_V_F   (NCH_SM*4*NTHR*4)           // float offset of s_v = 45056
#define SM_ZP_F  (SM_V_F + VBUF)             // float offset of zp
#define SM_TOT_B (SM_ZP_F*4 + 4*ZSTR*16)     // 218,432 B

__global__ __launch_bounds__(NTHR, 1)
void ltc_main(const float* __restrict__ x,
              const float* __restrict__ bf,
              const float* __restrict__ tau,
              const float* __restrict__ A,
              const float* __restrict__ Wo,
              const float* __restrict__ bo,
              float* __restrict__ out)
{
    extern __shared__ float sm[];
    ulonglong2* s_w  = (ulonglong2*)sm;
    float*      s_v  = sm + SM_V_F;
    ulonglong2* s_zp = (ulonglong2*)(sm + SM_ZP_F);

    const int tid  = threadIdx.x;
    const int lane = tid & 31;
    const int kb   = lane & 3;
    const int g    = (tid >> 5)*8 + (lane >> 2);  // 0..63
    const int row0 = blockIdx.x * ROWS;

    // ---- stage SMEM-W (coalesced) ----
    for (int e = 0; e < NCH_SM*4; e++) s_w[e*NTHR + tid] = g_Ws[e*NTHR + tid];

    // ---- W registers (56 ull = 112 regs) ----
    ull wr[56];
#pragma unroll
    for (int p = 0; p < 56; p++) wr[p] = g_Wr[p*NTHR + tid];

    // ---- updater constants: thread owns j = tid across all 4 rows ----
    const int uj = tid;
    const float bfj = bf[uj];
    const float itj = expf(-tau[uj]);
    const float Aj  = A[uj];
    float h0 = 0.f, h1 = 0.f, h2 = 0.f, h3 = 0.f;
    const int hk   = 64 + uj;
    const int hadr = (hk/KSL)*VS4 + (hk % KSL);

    // ---- x writer: each thread owns one (row, d) ----
    const int xr = tid >> 6, xd = tid & 63;
    const float* xptr = x + (size_t)(row0 + xr) * T_ * D_ + xd;
    const int xadr = xd;                      // k<64 lives in slice kb=0

    // ---- init v ----
    for (int i = tid; i < VBUF; i += NTHR) s_v[i] = 0.f;
    __syncthreads();
    s_v[xr*RSTR + xadr] = xptr[0];
    __syncthreads();

    const float* vbk = s_v + kb*VS4;
    const int jb2 = (g*4)*2;                  // zp j-offset (ulonglong2 units)

    // ================= recurrent loop =================
    for (int t = 0; t < T_; ++t) {
        // L2 wave A: chunk 18 (consumed ~1500 cyc later)
        ulonglong2 a0 = g_Wl[0*NTHR + tid];
        ulonglong2 a1 = g_Wl[1*NTHR + tid];
        ulonglong2 a2 = g_Wl[2*NTHR + tid];
        ulonglong2 a3 = g_Wl[3*NTHR + tid];

        float x_pre = (t + 1 < T_) ? xptr[(t + 1) * D_] : 0.f;

        ull acc[16];
#pragma unroll
        for (int i = 0; i < 16; i++) acc[i] = 0ull;

#define CH_FMA(W0,W1,W2,W3)                                                \
        {                                                                  \
            ulonglong2 v0 = *(const ulonglong2*)(vbk + 0*RSTR + q*4);      \
            ulonglong2 v1 = *(const ulonglong2*)(vbk + 1*RSTR + q*4);      \
            ulonglong2 v2 = *(const ulonglong2*)(vbk + 2*RSTR + q*4);      \
            ulonglong2 v3 = *(const ulonglong2*)(vbk + 3*RSTR + q*4);      \
            acc[ 0]=fma2(W0.x,v0.x,acc[ 0]); acc[ 0]=fma2(W0.y,v0.y,acc[ 0]); \
            acc[ 1]=fma2(W0.x,v1.x,acc[ 1]); acc[ 1]=fma2(W0.y,v1.y,acc[ 1]); \
            acc[ 2]=fma2(W0.x,v2.x,acc[ 2]); acc[ 2]=fma2(W0.y,v2.y,acc[ 2]); \
            acc[ 3]=fma2(W0.x,v3.x,acc[ 3]); acc[ 3]=fma2(W0.y,v3.y,acc[ 3]); \
            acc[ 4]=fma2(W1.x,v0.x,acc[ 4]); acc[ 4]=fma2(W1.y,v0.y,acc[ 4]); \
            acc[ 5]=fma2(W1.x,v1.x,acc[ 5]); acc[ 5]=fma2(W1.y,v1.y,acc[ 5]); \
            acc[ 6]=fma2(W1.x,v2.x,acc[ 6]); acc[ 6]=fma2(W1.y,v2.y,acc[ 6]); \
            acc[ 7]=fma2(W1.x,v3.x,acc[ 7]); acc[ 7]=fma2(W1.y,v3.y,acc[ 7]); \
            acc[ 8]=fma2(W2.x,v0.x,acc[ 8]); acc[ 8]=fma2(W2.y,v0.y,acc[ 8]); \
            acc[ 9]=fma2(W2.x,v1.x,acc[ 9]); acc[ 9]=fma2(W2.y,v1.y,acc[ 9]); \
            acc[10]=fma2(W2.x,v2.x,acc[10]); acc[10]=fma2(W2.y,v2.y,acc[10]); \
            acc[11]=fma2(W2.x,v3.x,acc[11]); acc[11]=fma2(W2.y,v3.y,acc[11]); \
            acc[12]=fma2(W3.x,v0.x,acc[12]); acc[12]=fma2(W3.y,v0.y,acc[12]); \
            acc[13]=fma2(W3.x,v1.x,acc[13]); acc[13]=fma2(W3.y,v1.y,acc[13]); \
            acc[14]=fma2(W3.x,v2.x,acc[14]); acc[14]=fma2(W3.y,v2.y,acc[14]); \
            acc[15]=fma2(W3.x,v3.x,acc[15]); acc[15]=fma2(W3.y,v3.y,acc[15]); \
        }

        // ---- chunks 0..6: W from registers ----
#pragma unroll
        for (int q = 0; q < NCH_RF; q++) {
            ulonglong2 W0 = make_ulonglong2(wr[(q*4+0)*2], wr[(q*4+0)*2+1]);
            ulonglong2 W1 = make_ulonglong2(wr[(q*4+1)*2], wr[(q*4+1)*2+1]);
            ulonglong2 W2 = make_ulonglong2(wr[(q*4+2)*2], wr[(q*4+2)*2+1]);
            ulonglong2 W3 = make_ulonglong2(wr[(q*4+3)*2], wr[(q*4+3)*2+1]);
            CH_FMA(W0, W1, W2, W3);
        }

        // ---- chunks 7..12: W from SMEM ----
#pragma unroll
        for (int q = 7; q < 13; q++) {
            ulonglong2 W0 = s_w[((q-7)*4+0)*NTHR + tid];
            ulonglong2 W1 = s_w[((q-7)*4+1)*NTHR + tid];
            ulonglong2 W2 = s_w[((q-7)*4+2)*NTHR + tid];
            ulonglong2 W3 = s_w[((q-7)*4+3)*NTHR + tid];
            CH_FMA(W0, W1, W2, W3);
        }

        // L2 wave B: chunk 19
        ulonglong2 b0 = g_Wl[4*NTHR + tid];
        ulonglong2 b1 = g_Wl[5*NTHR + tid];
        ulonglong2 b2 = g_Wl[6*NTHR + tid];
        ulonglong2 b3 = g_Wl[7*NTHR + tid];

        // ---- chunks 13..17: W from SMEM ----
#pragma unroll
        for (int q = 13; q < 18; q++) {
            ulonglong2 W0 = s_w[((q-7)*4+0)*NTHR + tid];
            ulonglong2 W1 = s_w[((q-7)*4+1)*NTHR + tid];
            ulonglong2 W2 = s_w[((q-7)*4+2)*NTHR + tid];
            ulonglong2 W3 = s_w[((q-7)*4+3)*NTHR + tid];
            CH_FMA(W0, W1, W2, W3);
        }

        // ---- chunks 18,19: W from L2 waves ----
        { const int q = 18; CH_FMA(a0, a1, a2, a3); }
        { const int q = 19; CH_FMA(b0, b1, b2, b3); }
#undef CH_FMA

        // ---- post packed partials: zp[kb][j][rpair] ----
#pragma unroll
        for (int jj = 0; jj < 4; jj++) {
            s_zp[kb*ZSTR + jb2 + jj*2 + 0] = make_ulonglong2(acc[jj*4+0], acc[jj*4+1]);
            s_zp[kb*ZSTR + jb2 + jj*2 + 1] = make_ulonglong2(acc[jj*4+2], acc[jj*4+3]);
        }
        __syncthreads();

        // ---- reduce 4 kb-partials + gate + state update (thread = j across 4 rows) ----
        {
            ulonglong2 p0a = s_zp[0*ZSTR + uj*2 + 0], p0b = s_zp[0*ZSTR + uj*2 + 1];
            ulonglong2 p1a = s_zp[1*ZSTR + uj*2 + 0], p1b = s_zp[1*ZSTR + uj*2 + 1];
            ulonglong2 p2a = s_zp[2*ZSTR + uj*2 + 0], p2b = s_zp[2*ZSTR + uj*2 + 1];
            ulonglong2 p3a = s_zp[3*ZSTR + uj*2 + 0], p3b = s_zp[3*ZSTR + uj*2 + 1];
            ull z0 = add2(add2(p0a.x, p1a.x), add2(p2a.x, p3a.x));
            ull z1 = add2(add2(p0a.y, p1a.y), add2(p2a.y, p3a.y));
            ull z2 = add2(add2(p0b.x, p1b.x), add2(p2b.x, p3b.x));
            ull z3 = add2(add2(p0b.y, p1b.y), add2(p2b.y, p3b.y));
#define GATE(Z, H)                                                          \
            {                                                               \
                float zf = __uint_as_float((unsigned)(Z))                   \
                         + __uint_as_float((unsigned)((Z) >> 32)) + bfj;    \
                float f  = __fdividef(1.f, 1.f + __expf(-zf));              \
                H += (-(itj + f) * H + f * Aj) * 0.1f;                      \
            }
            GATE(z0, h0); GATE(z1, h1); GATE(z2, h2); GATE(z3, h3);
#undef GATE
            s_v[0*RSTR + hadr] = h0;
            s_v[1*RSTR + hadr] = h1;
            s_v[2*RSTR + hadr] = h2;
            s_v[3*RSTR + hadr] = h3;
            s_v[xr*RSTR + xadr] = x_pre;
        }
        __syncthreads();
    }

    // ================= output projection =================
    float* s_hl = (float*)s_zp;           // [r][j]
    s_hl[0*256 + uj] = h0;
    s_hl[1*256 + uj] = h1;
    s_hl[2*256 + uj] = h2;
    s_hl[3*256 + uj] = h3;
    float* s_wo = (float*)s_w;            // reuse W region: [o][260]
    __syncthreads();
    for (int i = tid; i < 64*256; i += NTHR) {
        int o = i >> 8, q = i & 255;
        s_wo[o*260 + q] = Wo[i];
    }
    __syncthreads();

    {
        int r = tid >> 6, o = tid & 63;
        const float4* w4 = (const float4*)(s_wo + o*260);
        const float4* h4 = (const float4*)(s_hl + r*256);
        float s = bo[o];
#pragma unroll
        for (int q = 0; q < 64; q++) {
            float4 w = w4[q];
            float4 h = h4[q];
            s += w.x*h.x + w.y*h.y + w.z*h.z + w.w*h.w;
        }
        out[(row0 + r)*O_ + o] = s;
    }
}

extern "C" void kernel_launch(void* const* d_in, const int* in_sizes, int n_in,
                              void* d_out, int out_size)
{
    (void)in_sizes; (void)n_in; (void)out_size;
    const float* x   = (const float*)d_in[0];
    const float* Wf  = (const float*)d_in[1];
    const float* bf  = (const float*)d_in[2];
    const float* tau = (const float*)d_in[3];
    const float* A   = (const float*)d_in[4];
    const float* Wo  = (const float*)d_in[5];
    const float* bo  = (const float*)d_in[6];
    float* out = (float*)d_out;

    const int smem_bytes = SM_TOT_B;       // 218,432 B
    cudaFuncSetAttribute(ltc_main,
                         cudaFuncAttributeMaxDynamicSharedMemorySize, smem_bytes);

    ltc_prep<<<(80*NTHR + NTHR - 1) / NTHR, NTHR>>>(Wf);
    ltc_main<<<NCTA, NTHR, smem_bytes>>>(x, bf, tau, A, Wo, bo, out);
}

// round 13
// speedup vs baseline: 2.4752x; 1.0345x over previous
#include <cuda_runtime.h>
#include <cuda_fp16.h>
#include <cstdint>

// Problem dims
#define B_   512
#define T_   1024
#define D_   64
#define H_   256
#define O_   64
#define KTOT 320           // combined [x(64) | h(256)]

#define ROWS 4
#define NCTA (B_/ROWS)     // 128
#define NTHR 256
#define KSL  80            // k per kb-slice
#define VS4  84            // padded slice stride: kb bank-quads {0,5,2,7}
#define RSTR (4*VS4)       // 336 floats per row
#define VBUF (ROWS*RSTR)   // 1344 floats (single buffer)

// W chunk classes (20 chunks of 4 k per slice)
#define NCH_RF 7           // chunks 0..6   -> registers, fp32 (56 ull = 112 regs)
#define NCH_HM 13          // chunks 7..19  -> SMEM, fp16x4 (52 ull = 104 KB staged)

#define ZSTR 578           // zp kb-stride in ulonglong2: 578 mod 8 = 2 (conflict-free swizzle)

typedef unsigned long long ull;

__device__ ull g_Wr[NCH_RF*4*2*NTHR];   // fp32 pairs, 56*256 ull
__device__ ull g_Wsh[NCH_HM*4*NTHR];    // fp16x4,     52*256 ull

__device__ __forceinline__ ull fma2(ull a, ull b, ull c) {
    ull d; asm("fma.rn.f32x2 %0, %1, %2, %3;" : "=l"(d) : "l"(a), "l"(b), "l"(c));
    return d;
}
__device__ __forceinline__ ull add2(ull a, ull b) {
    ull d; asm("add.rn.f32x2 %0, %1, %2;" : "=l"(d) : "l"(a), "l"(b));
    return d;
}
// fp16x2 word -> packed f32x2 (register pair)
__device__ __forceinline__ ull h2f2(unsigned w) {
    ull d;
    asm("{\n\t"
        ".reg .b16 l, h;\n\t"
        ".reg .f32 fl, fh;\n\t"
        "mov.b32 {l, h}, %1;\n\t"
        "cvt.f32.f16 fl, l;\n\t"
        "cvt.f32.f16 fh, h;\n\t"
        "mov.b64 %0, {fl, fh};\n\t"
        "}" : "=l"(d) : "r"(w));
    return d;
}

// Pack Wf[H, D+H] into per-thread layouts. One prep thread per (chunk, jj, tid).
__global__ void ltc_prep(const float* __restrict__ Wf) {
    int idx = blockIdx.x * blockDim.x + threadIdx.x;
    if (idx >= 80*NTHR) return;
    int tid   = idx & (NTHR-1);
    int u2    = idx >> 8;            // 0..79
    int chunk = u2 >> 2, jj = u2 & 3;
    int lane = tid & 31;
    int kb   = lane & 3;
    int g    = (tid >> 5)*8 + (lane >> 2);   // 0..63
    int j    = g*4 + jj;
    int k0   = kb*KSL + chunk*4;
    const float* src = Wf + j*KTOT + k0;
    if (chunk < NCH_RF) {
        ull lo = ((ull)__float_as_uint(src[1]) << 32) | __float_as_uint(src[0]);
        ull hi = ((ull)__float_as_uint(src[3]) << 32) | __float_as_uint(src[2]);
        int p = (chunk*4 + jj)*2;
        g_Wr[(p+0)*NTHR + tid] = lo;
        g_Wr[(p+1)*NTHR + tid] = hi;
    } else {
        unsigned lo = (unsigned)__half_as_ushort(__float2half_rn(src[0]))
                    | ((unsigned)__half_as_ushort(__float2half_rn(src[1])) << 16);
        unsigned hi = (unsigned)__half_as_ushort(__float2half_rn(src[2]))
                    | ((unsigned)__half_as_ushort(__float2half_rn(src[3])) << 16);
        int e = (chunk - NCH_RF)*4 + jj;
        g_Wsh[e*NTHR + tid] = ((ull)hi << 32) | lo;
    }
}

// SMEM: s_wh 52*256 ull (106496 B) | s_v 1344 f (5376 B) | zp 4*578 ul2 (36992 B)
#define SM_V_F   (NCH_HM*4*NTHR*2)           // float offset of s_v = 26624
#define SM_ZP_F  (SM_V_F + VBUF)             // 27968 (byte 111872, 16B aligned)
#define SM_TOT_B (SM_ZP_F*4 + 4*ZSTR*16)     // 148,864 B

__global__ __launch_bounds__(NTHR, 1)
void ltc_main(const float* __restrict__ x,
              const float* __restrict__ bf,
              const float* __restrict__ tau,
              const float* __restrict__ A,
              const float* __restrict__ Wo,
              const float* __restrict__ bo,
              float* __restrict__ out)
{
    extern __shared__ float sm[];
    ull*        s_wh = (ull*)sm;
    float*      s_v  = sm + SM_V_F;
    ulonglong2* s_zp = (ulonglong2*)(sm + SM_ZP_F);

    const int tid  = threadIdx.x;
    const int lane = tid & 31;
    const int kb   = lane & 3;
    const int g    = (tid >> 5)*8 + (lane >> 2);  // 0..63
    const int row0 = blockIdx.x * ROWS;

    // ---- stage fp16 SMEM-W (coalesced LDG.64/STS.64) ----
    for (int e = 0; e < NCH_HM*4; e++) s_wh[e*NTHR + tid] = g_Wsh[e*NTHR + tid];

    // ---- W registers (56 ull = 112 regs, fp32 pairs) ----
    ull wr[56];
#pragma unroll
    for (int p = 0; p < 56; p++) wr[p] = g_Wr[p*NTHR + tid];

    // ---- updater constants: thread owns j = tid across all 4 rows ----
    const int uj = tid;
    const float bfj = bf[uj];
    const float itj = expf(-tau[uj]);
    const float Aj  = A[uj];
    float h0 = 0.f, h1 = 0.f, h2 = 0.f, h3 = 0.f;
    const int hk   = 64 + uj;
    const int hadr = (hk/KSL)*VS4 + (hk % KSL);

    // ---- x writer: each thread owns one (row, d) ----
    const int xr = tid >> 6, xd = tid & 63;
    const float* xptr = x + (size_t)(row0 + xr) * T_ * D_ + xd;
    const int xadr = xd;                      // k<64 lives in slice kb=0

    // ---- init v ----
    for (int i = tid; i < VBUF; i += NTHR) s_v[i] = 0.f;
    __syncthreads();
    s_v[xr*RSTR + xadr] = xptr[0];
    __syncthreads();

    const float* vbk = s_v + kb*VS4;
    const int jb9 = g*9;                      // swizzled zp j-offset (ul2 units)
    const int rb9 = (uj >> 2)*9 + (uj & 3)*2; // updater read offset

    // ================= recurrent loop =================
    for (int t = 0; t < T_; ++t) {
        float x_pre = (t + 1 < T_) ? xptr[(t + 1) * D_] : 0.f;

        ull acc[16];
#pragma unroll
        for (int i = 0; i < 16; i++) acc[i] = 0ull;

#define CH_FMA(W0,W1,W2,W3)                                                \
        {                                                                  \
            ulonglong2 v0 = *(const ulonglong2*)(vbk + 0*RSTR + q*4);      \
            ulonglong2 v1 = *(const ulonglong2*)(vbk + 1*RSTR + q*4);      \
            ulonglong2 v2 = *(const ulonglong2*)(vbk + 2*RSTR + q*4);      \
            ulonglong2 v3 = *(const ulonglong2*)(vbk + 3*RSTR + q*4);      \
            acc[ 0]=fma2(W0.x,v0.x,acc[ 0]); acc[ 0]=fma2(W0.y,v0.y,acc[ 0]); \
            acc[ 1]=fma2(W0.x,v1.x,acc[ 1]); acc[ 1]=fma2(W0.y,v1.y,acc[ 1]); \
            acc[ 2]=fma2(W0.x,v2.x,acc[ 2]); acc[ 2]=fma2(W0.y,v2.y,acc[ 2]); \
            acc[ 3]=fma2(W0.x,v3.x,acc[ 3]); acc[ 3]=fma2(W0.y,v3.y,acc[ 3]); \
            acc[ 4]=fma2(W1.x,v0.x,acc[ 4]); acc[ 4]=fma2(W1.y,v0.y,acc[ 4]); \
            acc[ 5]=fma2(W1.x,v1.x,acc[ 5]); acc[ 5]=fma2(W1.y,v1.y,acc[ 5]); \
            acc[ 6]=fma2(W1.x,v2.x,acc[ 6]); acc[ 6]=fma2(W1.y,v2.y,acc[ 6]); \
            acc[ 7]=fma2(W1.x,v3.x,acc[ 7]); acc[ 7]=fma2(W1.y,v3.y,acc[ 7]); \
            acc[ 8]=fma2(W2.x,v0.x,acc[ 8]); acc[ 8]=fma2(W2.y,v0.y,acc[ 8]); \
            acc[ 9]=fma2(W2.x,v1.x,acc[ 9]); acc[ 9]=fma2(W2.y,v1.y,acc[ 9]); \
            acc[10]=fma2(W2.x,v2.x,acc[10]); acc[10]=fma2(W2.y,v2.y,acc[10]); \
            acc[11]=fma2(W2.x,v3.x,acc[11]); acc[11]=fma2(W2.y,v3.y,acc[11]); \
            acc[12]=fma2(W3.x,v0.x,acc[12]); acc[12]=fma2(W3.y,v0.y,acc[12]); \
            acc[13]=fma2(W3.x,v1.x,acc[13]); acc[13]=fma2(W3.y,v1.y,acc[13]); \
            acc[14]=fma2(W3.x,v2.x,acc[14]); acc[14]=fma2(W3.y,v2.y,acc[14]); \
            acc[15]=fma2(W3.x,v3.x,acc[15]); acc[15]=fma2(W3.y,v3.y,acc[15]); \
        }

        // ---- chunks 0..6: W from registers (fp32) ----
#pragma unroll
        for (int q = 0; q < NCH_RF; q++) {
            ulonglong2 W0 = make_ulonglong2(wr[(q*4+0)*2], wr[(q*4+0)*2+1]);
            ulonglong2 W1 = make_ulonglong2(wr[(q*4+1)*2], wr[(q*4+1)*2+1]);
            ulonglong2 W2 = make_ulonglong2(wr[(q*4+2)*2], wr[(q*4+2)*2+1]);
            ulonglong2 W3 = make_ulonglong2(wr[(q*4+3)*2], wr[(q*4+3)*2+1]);
            CH_FMA(W0, W1, W2, W3);
        }

        // ---- chunks 7..19: W from SMEM (fp16x4 -> f32x2 pairs) ----
#pragma unroll
        for (int q = NCH_RF; q < 20; q++) {
            ull hw0 = s_wh[((q-NCH_RF)*4+0)*NTHR + tid];
            ull hw1 = s_wh[((q-NCH_RF)*4+1)*NTHR + tid];
            ull hw2 = s_wh[((q-NCH_RF)*4+2)*NTHR + tid];
            ull hw3 = s_wh[((q-NCH_RF)*4+3)*NTHR + tid];
            ulonglong2 W0 = make_ulonglong2(h2f2((unsigned)hw0), h2f2((unsigned)(hw0 >> 32)));
            ulonglong2 W1 = make_ulonglong2(h2f2((unsigned)hw1), h2f2((unsigned)(hw1 >> 32)));
            ulonglong2 W2 = make_ulonglong2(h2f2((unsigned)hw2), h2f2((unsigned)(hw2 >> 32)));
            ulonglong2 W3 = make_ulonglong2(h2f2((unsigned)hw3), h2f2((unsigned)(hw3 >> 32)));
            CH_FMA(W0, W1, W2, W3);
        }
#undef CH_FMA

        // ---- post packed partials (swizzled, conflict-free) ----
#pragma unroll
        for (int jj = 0; jj < 4; jj++) {
            s_zp[kb*ZSTR + jb9 + jj*2 + 0] = make_ulonglong2(acc[jj*4+0], acc[jj*4+1]);
            s_zp[kb*ZSTR + jb9 + jj*2 + 1] = make_ulonglong2(acc[jj*4+2], acc[jj*4+3]);
        }
        __syncthreads();

        // ---- reduce 4 kb-partials + gate + state update (thread = j, 4 rows) ----
        {
            ulonglong2 p0a = s_zp[0*ZSTR + rb9 + 0], p0b = s_zp[0*ZSTR + rb9 + 1];
            ulonglong2 p1a = s_zp[1*ZSTR + rb9 + 0], p1b = s_zp[1*ZSTR + rb9 + 1];
            ulonglong2 p2a = s_zp[2*ZSTR + rb9 + 0], p2b = s_zp[2*ZSTR + rb9 + 1];
            ulonglong2 p3a = s_zp[3*ZSTR + rb9 + 0], p3b = s_zp[3*ZSTR + rb9 + 1];
            ull z0 = add2(add2(p0a.x, p1a.x), add2(p2a.x, p3a.x));
            ull z1 = add2(add2(p0a.y, p1a.y), add2(p2a.y, p3a.y));
            ull z2 = add2(add2(p0b.x, p1b.x), add2(p2b.x, p3b.x));
            ull z3 = add2(add2(p0b.y, p1b.y), add2(p2b.y, p3b.y));
#define GATE(Z, H)                                                          \
            {                                                               \
                float zf = __uint_as_float((unsigned)(Z))                   \
                         + __uint_as_float((unsigned)((Z) >> 32)) + bfj;    \
                float f  = __fdividef(1.f, 1.f + __expf(-zf));              \
                H += (-(itj + f) * H + f * Aj) * 0.1f;                      \
            }
            GATE(z0, h0); GATE(z1, h1); GATE(z2, h2); GATE(z3, h3);
#undef GATE
            s_v[0*RSTR + hadr] = h0;
            s_v[1*RSTR + hadr] = h1;
            s_v[2*RSTR + hadr] = h2;
            s_v[3*RSTR + hadr] = h3;
            s_v[xr*RSTR + xadr] = x_pre;
        }
        __syncthreads();
    }

    // ================= output projection =================
    float* s_hl = (float*)s_zp;           // [r][j]
    s_hl[0*256 + uj] = h0;
    s_hl[1*256 + uj] = h1;
    s_hl[2*256 + uj] = h2;
    s_hl[3*256 + uj] = h3;
    float* s_wo = (float*)s_wh;           // reuse W region: [o][260]
    __syncthreads();
    for (int i = tid; i < 64*256; i += NTHR) {
        int o = i >> 8, q = i & 255;
        s_wo[o*260 + q] = Wo[i];
    }
    __syncthreads();

    {
        int r = tid >> 6, o = tid & 63;
        const float4* w4 = (const float4*)(s_wo + o*260);
        const float4* h4 = (const float4*)(s_hl + r*256);
        float s = bo[o];
#pragma unroll
        for (int q = 0; q < 64; q++) {
            float4 w = w4[q];
            float4 h = h4[q];
            s += w.x*h.x + w.y*h.y + w.z*h.z + w.w*h.w;
        }
        out[(row0 + r)*O_ + o] = s;
    }
}

extern "C" void kernel_launch(void* const* d_in, const int* in_sizes, int n_in,
                              void* d_out, int out_size)
{
    (void)in_sizes; (void)n_in; (void)out_size;
    const float* x   = (const float*)d_in[0];
    const float* Wf  = (const float*)d_in[1];
    const float* bf  = (const float*)d_in[2];
    const float* tau = (const float*)d_in[3];
    const float* A   = (const float*)d_in[4];
    const float* Wo  = (const float*)d_in[5];
    const float* bo  = (const float*)d_in[6];
    float* out = (float*)d_out;

    const int smem_bytes = SM_TOT_B;       // 148,864 B
    cudaFuncSetAttribute(ltc_main,
                         cudaFuncAttributeMaxDynamicSharedMemorySize, smem_bytes);

    ltc_prep<<<(80*NTHR + NTHR - 1) / NTHR, NTHR>>>(Wf);
    ltc_main<<<NCTA, NTHR, smem_bytes>>>(x, bf, tau, A, Wo, bo, out);
}

// round 14
// speedup vs baseline: 2.8006x; 1.1315x over previous
#include <cuda_runtime.h>
#include <cstdint>

// Problem dims
#define B_   512
#define T_   1024
#define D_   64
#define H_   256
#define O_   64
#define KTOT 320           // combined [x(64) | h(256)]

#define ROWS 4
#define NCTA (B_/ROWS)     // 128
#define NTHR 256
#define KSL  80            // k per kb-slice
#define VS4  84            // padded slice stride: kb bank-quads {0,5,2,7}
#define RSTR (4*VS4)       // 336 floats per row
#define VBUF (ROWS*RSTR)   // 1344 floats per buffer

// W chunk classes (20 chunks of 4 k per slice)
#define NCH_RF 7           // chunks 0..6   -> registers, fp32 (56 ull = 112 regs)
#define NCH_BM 13          // chunks 7..19  -> SMEM, bf16x4 (104 KB staged)

typedef unsigned long long ull;

__device__ ull        g_Wr[NCH_RF*4*2*NTHR];     // fp32 pairs
__device__ ulonglong2 g_Wsb[NCH_BM*2*NTHR];      // bf16x4 pairs: [chunk][jpair][tid]

__device__ __forceinline__ ull fma2(ull a, ull b, ull c) {
    ull d; asm("fma.rn.f32x2 %0, %1, %2, %3;" : "=l"(d) : "l"(a), "l"(b), "l"(c));
    return d;
}
__device__ __forceinline__ ull add2(ull a, ull b) {
    ull d; asm("add.rn.f32x2 %0, %1, %2;" : "=l"(d) : "l"(a), "l"(b));
    return d;
}
// two bf16 in a 32-bit word -> packed f32x2 (PRMT expansion, alu pipe)
__device__ __forceinline__ ull bf2f2(unsigned w) {
    unsigned lo = __byte_perm(w, 0, 0x1044);   // f32 of halfword0
    unsigned hi = __byte_perm(w, 0, 0x3244);   // f32 of halfword1
    return ((ull)hi << 32) | lo;
}
__device__ __forceinline__ unsigned f2bf(float f) {   // RN-even bf16
    unsigned u = __float_as_uint(f);
    return (u + 0x7FFFu + ((u >> 16) & 1u)) >> 16;
}

// Pack Wf[H, D+H] into per-thread layouts. One prep thread per (chunk, jj, tid).
__global__ void ltc_prep(const float* __restrict__ Wf) {
    int idx = blockIdx.x * blockDim.x + threadIdx.x;
    if (idx >= 80*NTHR) return;
    int tid   = idx & (NTHR-1);
    int u2    = idx >> 8;            // 0..79
    int chunk = u2 >> 2, jj = u2 & 3;
    int lane = tid & 31;
    int kb   = lane & 3;
    int g    = (tid >> 5)*8 + (lane >> 2);   // 0..63
    int j    = g*4 + jj;
    int k0   = kb*KSL + chunk*4;
    const float* src = Wf + j*KTOT + k0;
    if (chunk < NCH_RF) {
        ull lo = ((ull)__float_as_uint(src[1]) << 32) | __float_as_uint(src[0]);
        ull hi = ((ull)__float_as_uint(src[3]) << 32) | __float_as_uint(src[2]);
        int p = (chunk*4 + jj)*2;
        g_Wr[(p+0)*NTHR + tid] = lo;
        g_Wr[(p+1)*NTHR + tid] = hi;
    } else {
        ull v = (ull)f2bf(src[0])
              | ((ull)f2bf(src[1]) << 16)
              | ((ull)f2bf(src[2]) << 32)
              | ((ull)f2bf(src[3]) << 48);
        int cc = chunk - NCH_RF;
        // ulonglong2 [(cc*2 + jj/2)*NTHR + tid], .x for jj even, .y for jj odd
        ((ull*)g_Wsb)[((cc*2 + (jj >> 1))*NTHR + tid)*2 + (jj & 1)] = v;
    }
}

// SMEM: s_wb 26*256 ulonglong2 (106,496 B) | s_v 2*1344 floats (10,752 B)
#define SM_V_F   (NCH_BM*2*NTHR*4)           // float offset of s_v = 26624
#define SM_TOT_B ((SM_V_F + 2*VBUF)*4)       // 117,248 B

__global__ __launch_bounds__(NTHR, 1)
void ltc_main(const float* __restrict__ x,
              const float* __restrict__ bf,
              const float* __restrict__ tau,
              const float* __restrict__ A,
              const float* __restrict__ Wo,
              const float* __restrict__ bo,
              float* __restrict__ out)
{
    extern __shared__ float sm[];
    ulonglong2* s_wb = (ulonglong2*)sm;
    float*      s_v  = sm + SM_V_F;

    const int tid  = threadIdx.x;
    const int lane = tid & 31;
    const int kb   = lane & 3;
    const bool p1  = kb & 1;
    const bool p2  = kb & 2;
    const int g    = (tid >> 5)*8 + (lane >> 2);  // 0..63
    const int j0   = g*4;
    const int row0 = blockIdx.x * ROWS;

    // ---- stage bf16 SMEM-W (coalesced) ----
    for (int e = 0; e < NCH_BM*2; e++) s_wb[e*NTHR + tid] = g_Wsb[e*NTHR + tid];

    // ---- W registers (56 ull = 112 regs, fp32 pairs) ----
    ull wr[56];
#pragma unroll
    for (int p = 0; p < 56; p++) wr[p] = g_Wr[p*NTHR + tid];

    // ---- gate constants for owned j's (j0..j0+3); this thread updates row kb ----
    const float4 bf4  = *(const float4*)(bf  + j0);
    const float4 tau4 = *(const float4*)(tau + j0);
    const float4 A4   = *(const float4*)(A   + j0);
    const float it4x = expf(-tau4.x), it4y = expf(-tau4.y),
                it4z = expf(-tau4.z), it4w = expf(-tau4.w);
    float hst[4] = {0.f, 0.f, 0.f, 0.f};
    const int hbase = ((64 + j0)/KSL)*VS4 + (64 + j0) % KSL;  // 4-span never crosses slice

    // ---- x writer: each thread owns one (row, d) ----
    const int xr = tid >> 6, xd = tid & 63;
    const float* xptr = x + (size_t)(row0 + xr) * T_ * D_ + xd;

    // ---- init v buffer 0 ----
    for (int i = tid; i < VBUF; i += NTHR) s_v[i] = 0.f;
    __syncthreads();
    s_v[xr*RSTR + xd] = xptr[0];
    __syncthreads();

    // ================= recurrent loop =================
    for (int t = 0; t < T_; ++t) {
        const float* vb = s_v + (t & 1)*VBUF;
        float*       vn = s_v + ((t + 1) & 1)*VBUF;
        const float* vbk = vb + kb*VS4;

        float x_pre = (t + 1 < T_) ? xptr[(t + 1) * D_] : 0.f;

        ull acc[16];
#pragma unroll
        for (int i = 0; i < 16; i++) acc[i] = 0ull;

#define CH_FMA(W0,W1,W2,W3)                                                \
        {                                                                  \
            ulonglong2 v0 = *(const ulonglong2*)(vbk + 0*RSTR + q*4);      \
            ulonglong2 v1 = *(const ulonglong2*)(vbk + 1*RSTR + q*4);      \
            ulonglong2 v2 = *(const ulonglong2*)(vbk + 2*RSTR + q*4);      \
            ulonglong2 v3 = *(const ulonglong2*)(vbk + 3*RSTR + q*4);      \
            acc[ 0]=fma2(W0.x,v0.x,acc[ 0]); acc[ 0]=fma2(W0.y,v0.y,acc[ 0]); \
            acc[ 1]=fma2(W0.x,v1.x,acc[ 1]); acc[ 1]=fma2(W0.y,v1.y,acc[ 1]); \
            acc[ 2]=fma2(W0.x,v2.x,acc[ 2]); acc[ 2]=fma2(W0.y,v2.y,acc[ 2]); \
            acc[ 3]=fma2(W0.x,v3.x,acc[ 3]); acc[ 3]=fma2(W0.y,v3.y,acc[ 3]); \
            acc[ 4]=fma2(W1.x,v0.x,acc[ 4]); acc[ 4]=fma2(W1.y,v0.y,acc[ 4]); \
            acc[ 5]=fma2(W1.x,v1.x,acc[ 5]); acc[ 5]=fma2(W1.y,v1.y,acc[ 5]); \
            acc[ 6]=fma2(W1.x,v2.x,acc[ 6]); acc[ 6]=fma2(W1.y,v2.y,acc[ 6]); \
            acc[ 7]=fma2(W1.x,v3.x,acc[ 7]); acc[ 7]=fma2(W1.y,v3.y,acc[ 7]); \
            acc[ 8]=fma2(W2.x,v0.x,acc[ 8]); acc[ 8]=fma2(W2.y,v0.y,acc[ 8]); \
            acc[ 9]=fma2(W2.x,v1.x,acc[ 9]); acc[ 9]=fma2(W2.y,v1.y,acc[ 9]); \
            acc[10]=fma2(W2.x,v2.x,acc[10]); acc[10]=fma2(W2.y,v2.y,acc[10]); \
            acc[11]=fma2(W2.x,v3.x,acc[11]); acc[11]=fma2(W2.y,v3.y,acc[11]); \
            acc[12]=fma2(W3.x,v0.x,acc[12]); acc[12]=fma2(W3.y,v0.y,acc[12]); \
            acc[13]=fma2(W3.x,v1.x,acc[13]); acc[13]=fma2(W3.y,v1.y,acc[13]); \
            acc[14]=fma2(W3.x,v2.x,acc[14]); acc[14]=fma2(W3.y,v2.y,acc[14]); \
            acc[15]=fma2(W3.x,v3.x,acc[15]); acc[15]=fma2(W3.y,v3.y,acc[15]); \
        }

        // ---- chunks 0..6: W from registers (fp32) ----
#pragma unroll
        for (int q = 0; q < NCH_RF; q++) {
            ulonglong2 W0 = make_ulonglong2(wr[(q*4+0)*2], wr[(q*4+0)*2+1]);
            ulonglong2 W1 = make_ulonglong2(wr[(q*4+1)*2], wr[(q*4+1)*2+1]);
            ulonglong2 W2 = make_ulonglong2(wr[(q*4+2)*2], wr[(q*4+2)*2+1]);
            ulonglong2 W3 = make_ulonglong2(wr[(q*4+3)*2], wr[(q*4+3)*2+1]);
            CH_FMA(W0, W1, W2, W3);
        }

        // ---- chunks 7..19: W from SMEM (bf16x4 -> f32x2 via PRMT) ----
#pragma unroll
        for (int q = NCH_RF; q < 20; q++) {
            const int cc = q - NCH_RF;
            ulonglong2 e0 = s_wb[(cc*2 + 0)*NTHR + tid];  // jj0 (.x), jj1 (.y)
            ulonglong2 e1 = s_wb[(cc*2 + 1)*NTHR + tid];  // jj2 (.x), jj3 (.y)
            ulonglong2 W0 = make_ulonglong2(bf2f2((unsigned)e0.x), bf2f2((unsigned)(e0.x >> 32)));
            ulonglong2 W1 = make_ulonglong2(bf2f2((unsigned)e0.y), bf2f2((unsigned)(e0.y >> 32)));
            ulonglong2 W2 = make_ulonglong2(bf2f2((unsigned)e1.x), bf2f2((unsigned)(e1.x >> 32)));
            ulonglong2 W3 = make_ulonglong2(bf2f2((unsigned)e1.y), bf2f2((unsigned)(e1.y >> 32)));
            CH_FMA(W0, W1, W2, W3);
        }
#undef CH_FMA

        // ---- intra-quad transpose-reduce over kb (lane kb keeps row kb) ----
        ull zv[4];
#pragma unroll
        for (int jj = 0; jj < 4; jj++) {
            const int Ai = jj*4;
            ull s0 = p1 ? acc[Ai+0] : acc[Ai+1];
            ull s1 = p1 ? acc[Ai+2] : acc[Ai+3];
            ull r0 = __shfl_xor_sync(0xFFFFFFFFu, s0, 1);
            ull r1 = __shfl_xor_sync(0xFFFFFFFFu, s1, 1);
            ull u  = add2(p1 ? acc[Ai+1] : acc[Ai+0], r0);  // r = p1,   over lane pair
            ull w  = add2(p1 ? acc[Ai+3] : acc[Ai+2], r1);  // r = 2+p1, over lane pair
            ull s2 = p2 ? u : w;
            ull r2 = __shfl_xor_sync(0xFFFFFFFFu, s2, 2);
            zv[jj] = add2(p2 ? w : u, r2);                  // r = kb, over all 4 lanes
        }

        // ---- gate + state update (this thread: j0..j0+3, row = kb) ----
        {
            float zf0 = __uint_as_float((unsigned)zv[0]) + __uint_as_float((unsigned)(zv[0]>>32)) + bf4.x;
            float zf1 = __uint_as_float((unsigned)zv[1]) + __uint_as_float((unsigned)(zv[1]>>32)) + bf4.y;
            float zf2 = __uint_as_float((unsigned)zv[2]) + __uint_as_float((unsigned)(zv[2]>>32)) + bf4.z;
            float zf3 = __uint_as_float((unsigned)zv[3]) + __uint_as_float((unsigned)(zv[3]>>32)) + bf4.w;
            float f0 = __fdividef(1.f, 1.f + __expf(-zf0));
            float f1 = __fdividef(1.f, 1.f + __expf(-zf1));
            float f2 = __fdividef(1.f, 1.f + __expf(-zf2));
            float f3 = __fdividef(1.f, 1.f + __expf(-zf3));
            hst[0] += (-(it4x + f0)*hst[0] + f0*A4.x) * 0.1f;
            hst[1] += (-(it4y + f1)*hst[1] + f1*A4.y) * 0.1f;
            hst[2] += (-(it4z + f2)*hst[2] + f2*A4.z) * 0.1f;
            hst[3] += (-(it4w + f3)*hst[3] + f3*A4.w) * 0.1f;
            *(float4*)(vn + kb*RSTR + hbase) = make_float4(hst[0], hst[1], hst[2], hst[3]);
            vn[xr*RSTR + xd] = x_pre;
        }
        __syncthreads();
    }

    // ================= output projection =================
    // h_final: thread (g,kb) holds rows=kb for j0..j0+3.
    float* s_hl = (float*)sm;                 // [r][j], 1024 floats (reuse W region)
    float* s_wo = (float*)sm + 1024;          // [o][260]
    *(float4*)(s_hl + kb*256 + j0) = make_float4(hst[0], hst[1], hst[2], hst[3]);
    __syncthreads();
    for (int i = tid; i < 64*256; i += NTHR) {
        int o = i >> 8, q = i & 255;
        s_wo[o*260 + q] = Wo[i];
    }
    __syncthreads();

    {
        int r = tid >> 6, o = tid & 63;
        const float4* w4 = (const float4*)(s_wo + o*260);
        const float4* h4 = (const float4*)(s_hl + r*256);
        float s = bo[o];
#pragma unroll
        for (int q = 0; q < 64; q++) {
            float4 w = w4[q];
            float4 h = h4[q];
            s += w.x*h.x + w.y*h.y + w.z*h.z + w.w*h.w;
        }
        out[(row0 + r)*O_ + o] = s;
    }
}

extern "C" void kernel_launch(void* const* d_in, const int* in_sizes, int n_in,
                              void* d_out, int out_size)
{
    (void)in_sizes; (void)n_in; (void)out_size;
    const float* x   = (const float*)d_in[0];
    const float* Wf  = (const float*)d_in[1];
    const float* bf  = (const float*)d_in[2];
    const float* tau = (const float*)d_in[3];
    const float* A   = (const float*)d_in[4];
    const float* Wo  = (const float*)d_in[5];
    const float* bo  = (const float*)d_in[6];
    float* out = (float*)d_out;

    const int smem_bytes = SM_TOT_B;       // 117,248 B
    cudaFuncSetAttribute(ltc_main,
                         cudaFuncAttributeMaxDynamicSharedMemorySize, smem_bytes);

    ltc_prep<<<(80*NTHR + NTHR - 1) / NTHR, NTHR>>>(Wf);
    ltc_main<<<NCTA, NTHR, smem_bytes>>>(x, bf, tau, A, Wo, bo, out);
}